// round 11
// baseline (speedup 1.0000x reference)
#include <cuda_runtime.h>
#include <cuda_fp16.h>
#include <math.h>
#include <stdint.h>

// Problem constants
#define BB 16
#define QQ 64
#define CC 512
#define DD 512
#define D4 2048
#define MTOT (BB*CC)   // 8192

// Scratch (device globals: allocation-free rule)
__device__ float g_m[BB*CC];
__device__ float g_hp[4*BB*DD];                              // h partials (4-way c-split)
__device__ __align__(16) __half g_Ah[(size_t)MTOT*D4];       // 32 MB
__device__ __align__(16) __half g_Bh[(size_t)D4*D4];         // 8 MB

__device__ __forceinline__ uint32_t smem_u32(const void* p) {
    uint32_t a;
    asm("{ .reg .u64 t; cvta.to.shared.u64 t, %1; cvt.u32.u64 %0, t; }"
        : "=r"(a) : "l"(p));
    return a;
}

#define LDSM4(r, addr) \
    asm volatile("ldmatrix.sync.aligned.m8n8.x4.shared.b16 {%0,%1,%2,%3}, [%4];" \
        : "=r"((r)[0]), "=r"((r)[1]), "=r"((r)[2]), "=r"((r)[3]) : "r"(addr))

#define CP16(dst, src) \
    asm volatile("cp.async.cg.shared.global [%0], [%1], 16;" \
        :: "r"(dst), "l"(src) : "memory")

__device__ __forceinline__ void mma16816(float* d, const uint32_t* a,
                                         uint32_t b0, uint32_t b1) {
    asm volatile(
        "mma.sync.aligned.m16n8k16.row.col.f32.f16.f16.f32 "
        "{%0,%1,%2,%3}, {%4,%5,%6,%7}, {%8,%9}, {%0,%1,%2,%3};"
        : "+f"(d[0]), "+f"(d[1]), "+f"(d[2]), "+f"(d[3])
        : "r"(a[0]), "r"(a[1]), "r"(a[2]), "r"(a[3]), "r"(b0), "r"(b1));
}

__device__ __forceinline__ uint32_t pack2h(float x, float y) {
    __half hx = __float2half_rn(x), hy = __float2half_rn(y);
    return ((uint32_t)__half_as_ushort(hy) << 16) | (uint32_t)__half_as_ushort(hx);
}

// ---------------------------------------------------------------------------
// Kernel 1: per (b, 32-c-tile): sim tile (+fused row-dots) + softmax + u_tilde
// writes u (seg1) and u*ctx (seg2) of g_Ah directly as fp16.  [R8/R10 proven]
// 256 blocks (16 b x 16 c-tiles), 256 threads
// ---------------------------------------------------------------------------
__global__ __launch_bounds__(256) void k_sim_u(
    const float* __restrict__ questions,
    const float* __restrict__ contexts,
    const float* __restrict__ sim_w) {
    __shared__ float sh[2112 + 4352];
    __shared__ float s_cq[32], s_qq[64];
    int b  = blockIdx.x >> 4;
    int ct = blockIdx.x & 15;
    int tid = threadIdx.x;
    int tx = tid & 15, ty = tid >> 4;
    int wid = tid >> 5, lane = tid & 31;

    const float* wp  = sim_w + 2*DD;
    const float* wq  = sim_w + DD;
    const float* ctx = contexts + ((size_t)b*CC + ct*32) * DD;
    const float* qs  = questions + (size_t)b*QQ*DD;

    float acc[2][4];
    #pragma unroll
    for (int i = 0; i < 2; i++)
        #pragma unroll
        for (int j = 0; j < 4; j++) acc[i][j] = 0.f;

    float* s_a = sh;            // [32k][32row]
    float* s_b = sh + 1024;     // [32k][64row]

    float cqp = 0.f;
    float qqp = 0.f;

    for (int k0 = 0; k0 < DD; k0 += 32) {
        __syncthreads();
        {
            int row = tid >> 3, kq = tid & 7;
            float4 av = *(const float4*)(ctx + (size_t)row*DD + k0 + kq*4);
            float4 wv = *(const float4*)(wp + k0 + kq*4);
            float4 wc = *(const float4*)(sim_w + k0 + kq*4);
            cqp += av.x*wc.x + av.y*wc.y + av.z*wc.z + av.w*wc.w;
            s_a[(kq*4+0)*32 + row] = av.x * wv.x;
            s_a[(kq*4+1)*32 + row] = av.y * wv.y;
            s_a[(kq*4+2)*32 + row] = av.z * wv.z;
            s_a[(kq*4+3)*32 + row] = av.w * wv.w;
        }
        #pragma unroll
        for (int i = 0; i < 2; i++) {
            int li = tid*2 + i;
            int row = li >> 3, kq = li & 7;
            float4 qv = *(const float4*)(qs + (size_t)row*DD + k0 + kq*4);
            float4 wv = *(const float4*)(wq + k0 + kq*4);
            qqp += qv.x*wv.x + qv.y*wv.y + qv.z*wv.z + qv.w*wv.w;
            s_b[(kq*4+0)*64 + row] = qv.x;
            s_b[(kq*4+1)*64 + row] = qv.y;
            s_b[(kq*4+2)*64 + row] = qv.z;
            s_b[(kq*4+3)*64 + row] = qv.w;
        }
        __syncthreads();
        #pragma unroll
        for (int k = 0; k < 32; k++) {
            float2 av = *(float2*)&s_a[k*32 + ty*2];
            float4 bv = *(float4*)&s_b[k*64 + tx*4];
            float b4[4] = {bv.x, bv.y, bv.z, bv.w};
            #pragma unroll
            for (int j = 0; j < 4; j++) {
                acc[0][j] += av.x * b4[j];
                acc[1][j] += av.y * b4[j];
            }
        }
    }

    {
        float s = cqp;
        s += __shfl_xor_sync(0xffffffffu, s, 1);
        s += __shfl_xor_sync(0xffffffffu, s, 2);
        s += __shfl_xor_sync(0xffffffffu, s, 4);
        if ((tid & 7) == 0) s_cq[tid >> 3] = s;
        float t = qqp;
        t += __shfl_xor_sync(0xffffffffu, t, 1);
        t += __shfl_xor_sync(0xffffffffu, t, 2);
        if ((tid & 3) == 0) s_qq[tid >> 2] = t;
    }
    __syncthreads();

    float* s_sim = sh;          // [32][66]
    #pragma unroll
    for (int i = 0; i < 2; i++) {
        float cqv = s_cq[ty*2 + i];
        #pragma unroll
        for (int j = 0; j < 4; j++)
            s_sim[(ty*2+i)*66 + tx*4 + j] = acc[i][j] + cqv + s_qq[tx*4 + j];
    }
    __syncthreads();

    #pragma unroll
    for (int rr = 0; rr < 4; rr++) {
        int r = wid*4 + rr;
        float v0 = s_sim[r*66 + lane];
        float v1 = s_sim[r*66 + 32 + lane];
        float mx = fmaxf(v0, v1);
        #pragma unroll
        for (int o = 16; o > 0; o >>= 1) mx = fmaxf(mx, __shfl_xor_sync(0xffffffffu, mx, o));
        float e0 = __expf(v0 - mx), e1 = __expf(v1 - mx);
        float sm = e0 + e1;
        #pragma unroll
        for (int o = 16; o > 0; o >>= 1) sm += __shfl_xor_sync(0xffffffffu, sm, o);
        float inv = 1.f / sm;
        s_sim[r*66 + lane]      = e0 * inv;
        s_sim[r*66 + 32 + lane] = e1 * inv;
        if (lane == 0) g_m[b*CC + ct*32 + r] = mx;
    }
    __syncthreads();

    float* s_q2 = sh + 2112;    // [64][68]
    for (int d0 = 0; d0 < DD; d0 += 64) {
        #pragma unroll
        for (int i = 0; i < 4; i++) {
            int li  = tid + i*256;
            int row = li >> 4;
            int dq  = li & 15;
            float4 qv = *(const float4*)(qs + (size_t)row*DD + d0 + dq*4);
            *(float4*)&s_q2[row*68 + dq*4] = qv;
        }
        __syncthreads();
        float a2[2][4];
        #pragma unroll
        for (int i = 0; i < 2; i++)
            #pragma unroll
            for (int j = 0; j < 4; j++) a2[i][j] = 0.f;
        #pragma unroll 8
        for (int k = 0; k < 64; k++) {
            float p0 = s_sim[(ty*2+0)*66 + k];
            float p1 = s_sim[(ty*2+1)*66 + k];
            float4 qv = *(float4*)&s_q2[k*68 + tx*4];
            float q4[4] = {qv.x, qv.y, qv.z, qv.w};
            #pragma unroll
            for (int j = 0; j < 4; j++) {
                a2[0][j] += p0 * q4[j];
                a2[1][j] += p1 * q4[j];
            }
        }
        #pragma unroll
        for (int i = 0; i < 2; i++) {
            int lrow = ty*2 + i;
            size_t m = (size_t)b*CC + ct*32 + lrow;
            float4 cv = *(const float4*)(ctx + (size_t)lrow*DD + d0 + tx*4);
            uint2 uh, uc;
            uh.x = pack2h(a2[i][0], a2[i][1]);
            uh.y = pack2h(a2[i][2], a2[i][3]);
            uc.x = pack2h(a2[i][0]*cv.x, a2[i][1]*cv.y);
            uc.y = pack2h(a2[i][2]*cv.z, a2[i][3]*cv.w);
            *(uint2*)&g_Ah[m*D4 + 512  + d0 + tx*4] = uh;
            *(uint2*)&g_Ah[m*D4 + 1024 + d0 + tx*4] = uc;
        }
        __syncthreads();
    }
}

// ---------------------------------------------------------------------------
// Kernel 2: h_tilde partials with fused attn softmax  [R10, unchanged]
// ---------------------------------------------------------------------------
__global__ void k_h(const float* __restrict__ contexts) {
    __shared__ float smm[512];
    __shared__ float red[128];
    __shared__ float sa[128];
    __shared__ float part[128];
    int bid = blockIdx.x;
    int cs = bid & 3;
    int dc = (bid >> 2) & 7;
    int b  = bid >> 5;
    int tid = threadIdx.x;
    #pragma unroll
    for (int i = 0; i < 4; i++) smm[tid + i*128] = g_m[b*CC + tid + i*128];
    __syncthreads();
    float mx = fmaxf(fmaxf(smm[tid], smm[tid+128]), fmaxf(smm[tid+256], smm[tid+384]));
    red[tid] = mx; __syncthreads();
    for (int s = 64; s > 0; s >>= 1) {
        if (tid < s) red[tid] = fmaxf(red[tid], red[tid + s]);
        __syncthreads();
    }
    mx = red[0]; __syncthreads();
    float sv = __expf(smm[tid]-mx) + __expf(smm[tid+128]-mx)
             + __expf(smm[tid+256]-mx) + __expf(smm[tid+384]-mx);
    red[tid] = sv; __syncthreads();
    for (int s = 64; s > 0; s >>= 1) {
        if (tid < s) red[tid] += red[tid + s];
        __syncthreads();
    }
    float inv = 1.f / red[0];
    sa[tid] = __expf(smm[cs*128 + tid] - mx) * inv;
    __syncthreads();
    int d = dc*64 + (tid & 63);
    int h = tid >> 6;
    const float* ctx = contexts + ((size_t)b*CC + cs*128 + h*64)*DD;
    float acc = 0.f;
    #pragma unroll 8
    for (int c = 0; c < 64; c++) acc += sa[h*64 + c] * ctx[(size_t)c*DD + d];
    part[tid] = acc;
    __syncthreads();
    if (h == 0) g_hp[((size_t)b*4 + cs)*DD + d] = part[tid] + part[tid + 64];
}

// ---------------------------------------------------------------------------
// Kernel 3: A seg0/seg3 -> fp16, and qac_w -> fp16 (merged)   [R10, unchanged]
// ---------------------------------------------------------------------------
__global__ void k_mm(const float* __restrict__ contexts,
                     const float* __restrict__ qac_w) {
    int bid = blockIdx.x;
    int tid = threadIdx.x;
    if (bid < 8192) {
        int m = bid;
        int b = m >> 9;
        uint2 h4;
        if (tid < 128) {
            int off = tid*4;
            float4 cv = *(const float4*)(contexts + (size_t)m*DD + off);
            h4.x = pack2h(cv.x, cv.y);
            h4.y = pack2h(cv.z, cv.w);
            *(uint2*)&g_Ah[(size_t)m*D4 + off] = h4;
        } else {
            int off = (tid - 128)*4;
            float4 cv = *(const float4*)(contexts + (size_t)m*DD + off);
            const float* hp = g_hp + (size_t)b*4*DD + off;
            float4 h0 = *(const float4*)(hp);
            float4 h1 = *(const float4*)(hp + DD);
            float4 h2 = *(const float4*)(hp + 2*DD);
            float4 h3 = *(const float4*)(hp + 3*DD);
            float hx = h0.x+h1.x+h2.x+h3.x;
            float hy = h0.y+h1.y+h2.y+h3.y;
            float hz = h0.z+h1.z+h2.z+h3.z;
            float hw = h0.w+h1.w+h2.w+h3.w;
            h4.x = pack2h(cv.x*hx, cv.y*hy);
            h4.y = pack2h(cv.z*hz, cv.w*hw);
            *(uint2*)&g_Ah[(size_t)m*D4 + 1536 + off] = h4;
        }
    } else {
        size_t i4 = (size_t)(bid - 8192)*256 + tid;   // D4*D4/4
        float4 v = ((const float4*)qac_w)[i4];
        uint2 h4;
        h4.x = pack2h(v.x, v.y);
        h4.y = pack2h(v.z, v.w);
        ((uint2*)g_Bh)[i4] = h4;
    }
}

// ---------------------------------------------------------------------------
// Kernel 4: mma.sync fp16 GEMM (single term, K = 2048)
// CTA tile 128x256, 8 warps (2Mx4N), warp tile 64x64, mma.m16n8k16.
// 32 K-iters of 64; 3-stage cp.async pipeline (54 KB/stage), 1 CTA/SM.
// Rationale: halves smem bytes/FLOP vs 128x128 (crossbar-bound at 51% tensor).
// ---------------------------------------------------------------------------
#define ROWB 144
#define ATILE (128*ROWB)         // 18432 B
#define BTILE (256*ROWB)         // 36864 B
#define STG1B (ATILE + BTILE)    // 55296 B per stage
#define GSMEM2 (3*STG1B)         // 165888 B

__global__ __launch_bounds__(256) void k_gemm_mma(
    const float* __restrict__ bias, float* __restrict__ out) {
    extern __shared__ char smem[];
    uint32_t su = smem_u32(smem);
    int tid  = threadIdx.x;
    int lane = tid & 31;
    int w    = tid >> 5;
    int wm   = w >> 2;          // 0..1 (M 64-half)
    int wn   = w & 3;           // 0..3 (N 64-quarter)
    int n0 = blockIdx.x * 256;
    int m0 = blockIdx.y * 128;

    float acc[4][8][4];
    #pragma unroll
    for (int i = 0; i < 4; i++)
        #pragma unroll
        for (int p = 0; p < 8; p++)
            #pragma unroll
            for (int e = 0; e < 4; e++) acc[i][p][e] = 0.f;

    int lrow = tid >> 3;        // 0..31
    int lchk = tid & 7;         // 16B chunk within 128B row

    auto load_stage = [&](int it, int s) {
        int kbase = it * 64;
        uint32_t sb = su + s*STG1B;
        #pragma unroll
        for (int i = 0; i < 4; i++) {
            int row = lrow + i*32;
            size_t aoff = (size_t)(m0 + row)*D4 + kbase + lchk*8;
            CP16(sb + row*ROWB + lchk*16, (const void*)(g_Ah + aoff));
        }
        #pragma unroll
        for (int i = 0; i < 8; i++) {
            int row = lrow + i*32;
            size_t boff = (size_t)(n0 + row)*D4 + kbase + lchk*8;
            CP16(sb + ATILE + row*ROWB + lchk*16, (const void*)(g_Bh + boff));
        }
        asm volatile("cp.async.commit_group;" ::: "memory");
    };

    load_stage(0, 0);
    load_stage(1, 1);

    int lr16 = (lane & 7) + ((lane >> 3) & 1) * 8;   // row 0..15
    int lc16 = lane >> 4;                             // chunk 0/1

    for (int it = 0; it < 32; it++) {
        int s = it % 3;
        if (it < 31) {
            asm volatile("cp.async.wait_group %0;" :: "n"(1) : "memory");
        } else {
            asm volatile("cp.async.wait_group %0;" :: "n"(0) : "memory");
        }
        __syncthreads();

        if (it + 2 < 32) load_stage(it + 2, (it + 2) % 3);

        uint32_t base = su + s*STG1B;
        uint32_t aW = base + (wm*64 + lr16)*ROWB + lc16*16;
        uint32_t bW = base + ATILE + (wn*64 + lr16)*ROWB + lc16*16;

        #pragma unroll
        for (int j = 0; j < 4; j++) {
            uint32_t af[4][4];
            #pragma unroll
            for (int i = 0; i < 4; i++)
                LDSM4(af[i], aW + i*16*ROWB + j*32);
            uint32_t bf[4][4];
            #pragma unroll
            for (int h = 0; h < 4; h++)
                LDSM4(bf[h], bW + h*16*ROWB + j*32);
            #pragma unroll
            for (int i = 0; i < 4; i++)
                #pragma unroll
                for (int p = 0; p < 8; p++)
                    mma16816(acc[i][p], af[i], bf[p>>1][p&1], bf[p>>1][(p&1)+2]);
        }
    }

    // Epilogue
    int g = lane >> 2, t = lane & 3;
    #pragma unroll
    for (int i = 0; i < 4; i++) {
        int row = m0 + wm*64 + i*16 + g;
        #pragma unroll
        for (int p = 0; p < 8; p++) {
            int col = n0 + wn*64 + p*8 + 2*t;
            float b0 = bias[col], b1 = bias[col + 1];
            float2 v0 = make_float2(acc[i][p][0] + b0, acc[i][p][1] + b1);
            float2 v1 = make_float2(acc[i][p][2] + b0, acc[i][p][3] + b1);
            *(float2*)(out + (size_t)row*D4 + col)       = v0;
            *(float2*)(out + (size_t)(row + 8)*D4 + col) = v1;
        }
    }
}

// ---------------------------------------------------------------------------
extern "C" void kernel_launch(void* const* d_in, const int* in_sizes, int n_in,
                              void* d_out, int out_size) {
    const float* questions = (const float*)d_in[0];
    const float* contexts  = (const float*)d_in[1];
    const float* sim_w     = (const float*)d_in[2];
    const float* qac_w     = (const float*)d_in[3];
    const float* qac_b     = (const float*)d_in[4];
    float* out = (float*)d_out;

    cudaFuncSetAttribute(k_gemm_mma, cudaFuncAttributeMaxDynamicSharedMemorySize, GSMEM2);

    k_sim_u<<<256, 256>>>(questions, contexts, sim_w);
    k_h<<<512, 128>>>(contexts);
    k_mm<<<12288, 256>>>(contexts, qac_w);
    k_gemm_mma<<<dim3(8, 64), 256, GSMEM2>>>(qac_b, out);
}

// round 12
// speedup vs baseline: 1.1527x; 1.1527x over previous
#include <cuda_runtime.h>
#include <cuda_fp16.h>
#include <math.h>
#include <stdint.h>

// Problem constants
#define BB 16
#define QQ 64
#define CC 512
#define DD 512
#define D4 2048
#define MTOT (BB*CC)   // 8192

// Scratch (device globals: allocation-free rule)
__device__ float g_m[BB*CC];
__device__ float g_hp[4*BB*DD];                              // h partials (4-way c-split)
__device__ __align__(16) __half g_Ah[(size_t)MTOT*D4];       // 32 MB
__device__ __align__(16) __half g_Bh[(size_t)D4*D4];         // 8 MB

__device__ __forceinline__ uint32_t smem_u32(const void* p) {
    uint32_t a;
    asm("{ .reg .u64 t; cvta.to.shared.u64 t, %1; cvt.u32.u64 %0, t; }"
        : "=r"(a) : "l"(p));
    return a;
}

#define LDSM4(r, addr) \
    asm volatile("ldmatrix.sync.aligned.m8n8.x4.shared.b16 {%0,%1,%2,%3}, [%4];" \
        : "=r"((r)[0]), "=r"((r)[1]), "=r"((r)[2]), "=r"((r)[3]) : "r"(addr))

#define CP16(dst, src) \
    asm volatile("cp.async.cg.shared.global [%0], [%1], 16;" \
        :: "r"(dst), "l"(src) : "memory")

__device__ __forceinline__ void mma16816(float* d, const uint32_t* a,
                                         uint32_t b0, uint32_t b1) {
    asm volatile(
        "mma.sync.aligned.m16n8k16.row.col.f32.f16.f16.f32 "
        "{%0,%1,%2,%3}, {%4,%5,%6,%7}, {%8,%9}, {%0,%1,%2,%3};"
        : "+f"(d[0]), "+f"(d[1]), "+f"(d[2]), "+f"(d[3])
        : "r"(a[0]), "r"(a[1]), "r"(a[2]), "r"(a[3]), "r"(b0), "r"(b1));
}

__device__ __forceinline__ uint32_t pack2h(float x, float y) {
    __half hx = __float2half_rn(x), hy = __float2half_rn(y);
    return ((uint32_t)__half_as_ushort(hy) << 16) | (uint32_t)__half_as_ushort(hx);
}

// ---------------------------------------------------------------------------
// Kernel 1: per (b, 32-c-tile): sim tile (+fused row-dots) + softmax + u_tilde
// Register-prefetch pipelined gmem loads (phase A and phase C).
// writes u (seg1) and u*ctx (seg2) of g_Ah directly as fp16.
// 256 blocks (16 b x 16 c-tiles), 256 threads
// ---------------------------------------------------------------------------
__global__ __launch_bounds__(256) void k_sim_u(
    const float* __restrict__ questions,
    const float* __restrict__ contexts,
    const float* __restrict__ sim_w) {
    __shared__ float sh[2112 + 4352];
    __shared__ float s_cq[32], s_qq[64];
    int b  = blockIdx.x >> 4;
    int ct = blockIdx.x & 15;
    int tid = threadIdx.x;
    int tx = tid & 15, ty = tid >> 4;
    int wid = tid >> 5, lane = tid & 31;

    const float* wp  = sim_w + 2*DD;
    const float* wq  = sim_w + DD;
    const float* ctx = contexts + ((size_t)b*CC + ct*32) * DD;
    const float* qs  = questions + (size_t)b*QQ*DD;

    float acc[2][4];
    #pragma unroll
    for (int i = 0; i < 2; i++)
        #pragma unroll
        for (int j = 0; j < 4; j++) acc[i][j] = 0.f;

    float* s_a = sh;            // [32k][32row]
    float* s_b = sh + 1024;     // [32k][64row]

    float cqp = 0.f;
    float qqp = 0.f;

    // fixed loader lanes
    int rowA = tid >> 3, kqA = tid & 7;            // A: 32 rows x 8 f4
    int row0 = (tid*2)   >> 3, kq0 = (tid*2)   & 7; // B: 64 rows x 8 f4 (two per thread)
    int row1 = (tid*2+1) >> 3, kq1 = (tid*2+1) & 7;

    // prologue loads, chunk k0 = 0
    float4 rA  = *(const float4*)(ctx + (size_t)rowA*DD + kqA*4);
    float4 rQ0 = *(const float4*)(qs  + (size_t)row0*DD + kq0*4);
    float4 rQ1 = *(const float4*)(qs  + (size_t)row1*DD + kq1*4);

    // Phase A: sim[32c x 64q], K=512 in chunks of 32, reg-prefetch pipelined
    for (int k0 = 0; k0 < DD; k0 += 32) {
        // store current regs -> smem, fused row-dot accumulation
        {
            float4 wv = *(const float4*)(wp + k0 + kqA*4);
            float4 wc = *(const float4*)(sim_w + k0 + kqA*4);
            cqp += rA.x*wc.x + rA.y*wc.y + rA.z*wc.z + rA.w*wc.w;
            s_a[(kqA*4+0)*32 + rowA] = rA.x * wv.x;
            s_a[(kqA*4+1)*32 + rowA] = rA.y * wv.y;
            s_a[(kqA*4+2)*32 + rowA] = rA.z * wv.z;
            s_a[(kqA*4+3)*32 + rowA] = rA.w * wv.w;

            float4 w0 = *(const float4*)(wq + k0 + kq0*4);
            qqp += rQ0.x*w0.x + rQ0.y*w0.y + rQ0.z*w0.z + rQ0.w*w0.w;
            s_b[(kq0*4+0)*64 + row0] = rQ0.x;
            s_b[(kq0*4+1)*64 + row0] = rQ0.y;
            s_b[(kq0*4+2)*64 + row0] = rQ0.z;
            s_b[(kq0*4+3)*64 + row0] = rQ0.w;

            float4 w1 = *(const float4*)(wq + k0 + kq1*4);
            qqp += rQ1.x*w1.x + rQ1.y*w1.y + rQ1.z*w1.z + rQ1.w*w1.w;
            s_b[(kq1*4+0)*64 + row1] = rQ1.x;
            s_b[(kq1*4+1)*64 + row1] = rQ1.y;
            s_b[(kq1*4+2)*64 + row1] = rQ1.z;
            s_b[(kq1*4+3)*64 + row1] = rQ1.w;
        }
        __syncthreads();

        // prefetch next chunk into regs (overlaps with compute below)
        float4 nA, nQ0, nQ1;
        if (k0 + 32 < DD) {
            nA  = *(const float4*)(ctx + (size_t)rowA*DD + k0 + 32 + kqA*4);
            nQ0 = *(const float4*)(qs  + (size_t)row0*DD + k0 + 32 + kq0*4);
            nQ1 = *(const float4*)(qs  + (size_t)row1*DD + k0 + 32 + kq1*4);
        } else {
            nA = rA; nQ0 = rQ0; nQ1 = rQ1;
        }

        #pragma unroll
        for (int k = 0; k < 32; k++) {
            float2 av = *(float2*)&s_a[k*32 + ty*2];
            float4 bv = *(float4*)&s_b[k*64 + tx*4];
            float b4[4] = {bv.x, bv.y, bv.z, bv.w};
            #pragma unroll
            for (int j = 0; j < 4; j++) {
                acc[0][j] += av.x * b4[j];
                acc[1][j] += av.y * b4[j];
            }
        }
        __syncthreads();
        rA = nA; rQ0 = nQ0; rQ1 = nQ1;
    }

    // Reduce fused row-dots: cq (8 lanes/row), qq (4 lanes/row)
    {
        float s = cqp;
        s += __shfl_xor_sync(0xffffffffu, s, 1);
        s += __shfl_xor_sync(0xffffffffu, s, 2);
        s += __shfl_xor_sync(0xffffffffu, s, 4);
        if ((tid & 7) == 0) s_cq[tid >> 3] = s;
        float t = qqp;
        t += __shfl_xor_sync(0xffffffffu, t, 1);
        t += __shfl_xor_sync(0xffffffffu, t, 2);
        if ((tid & 3) == 0) s_qq[tid >> 2] = t;
    }
    __syncthreads();

    // Phase B: add cq/qq, write sim, per-row softmax (Q=64), rowmax -> g_m
    float* s_sim = sh;          // [32][66]
    #pragma unroll
    for (int i = 0; i < 2; i++) {
        float cqv = s_cq[ty*2 + i];
        #pragma unroll
        for (int j = 0; j < 4; j++)
            s_sim[(ty*2+i)*66 + tx*4 + j] = acc[i][j] + cqv + s_qq[tx*4 + j];
    }
    __syncthreads();

    #pragma unroll
    for (int rr = 0; rr < 4; rr++) {
        int r = wid*4 + rr;
        float v0 = s_sim[r*66 + lane];
        float v1 = s_sim[r*66 + 32 + lane];
        float mx = fmaxf(v0, v1);
        #pragma unroll
        for (int o = 16; o > 0; o >>= 1) mx = fmaxf(mx, __shfl_xor_sync(0xffffffffu, mx, o));
        float e0 = __expf(v0 - mx), e1 = __expf(v1 - mx);
        float sm = e0 + e1;
        #pragma unroll
        for (int o = 16; o > 0; o >>= 1) sm += __shfl_xor_sync(0xffffffffu, sm, o);
        float inv = 1.f / sm;
        s_sim[r*66 + lane]      = e0 * inv;
        s_sim[r*66 + 32 + lane] = e1 * inv;
        if (lane == 0) g_m[b*CC + ct*32 + r] = mx;
    }
    __syncthreads();

    // Phase C: u[32 x 512] = P[32x64] @ qs[64x512], reg-prefetch pipelined
    float* s_q2 = sh + 2112;    // [64][68]
    int rowC[4], dqC[4];
    #pragma unroll
    for (int i = 0; i < 4; i++) {
        int li = tid + i*256;
        rowC[i] = li >> 4;
        dqC[i]  = li & 15;
    }
    float4 rq[4];
    #pragma unroll
    for (int i = 0; i < 4; i++)
        rq[i] = *(const float4*)(qs + (size_t)rowC[i]*DD + dqC[i]*4);

    for (int d0 = 0; d0 < DD; d0 += 64) {
        #pragma unroll
        for (int i = 0; i < 4; i++)
            *(float4*)&s_q2[rowC[i]*68 + dqC[i]*4] = rq[i];
        __syncthreads();

        float4 rqn[4];
        if (d0 + 64 < DD) {
            #pragma unroll
            for (int i = 0; i < 4; i++)
                rqn[i] = *(const float4*)(qs + (size_t)rowC[i]*DD + d0 + 64 + dqC[i]*4);
        } else {
            #pragma unroll
            for (int i = 0; i < 4; i++) rqn[i] = rq[i];
        }

        float a2[2][4];
        #pragma unroll
        for (int i = 0; i < 2; i++)
            #pragma unroll
            for (int j = 0; j < 4; j++) a2[i][j] = 0.f;
        #pragma unroll 8
        for (int k = 0; k < 64; k++) {
            float p0 = s_sim[(ty*2+0)*66 + k];
            float p1 = s_sim[(ty*2+1)*66 + k];
            float4 qv = *(float4*)&s_q2[k*68 + tx*4];
            float q4[4] = {qv.x, qv.y, qv.z, qv.w};
            #pragma unroll
            for (int j = 0; j < 4; j++) {
                a2[0][j] += p0 * q4[j];
                a2[1][j] += p1 * q4[j];
            }
        }
        #pragma unroll
        for (int i = 0; i < 2; i++) {
            int lrow = ty*2 + i;
            size_t m = (size_t)b*CC + ct*32 + lrow;
            float4 cv = *(const float4*)(ctx + (size_t)lrow*DD + d0 + tx*4);
            uint2 uh, uc;
            uh.x = pack2h(a2[i][0], a2[i][1]);
            uh.y = pack2h(a2[i][2], a2[i][3]);
            uc.x = pack2h(a2[i][0]*cv.x, a2[i][1]*cv.y);
            uc.y = pack2h(a2[i][2]*cv.z, a2[i][3]*cv.w);
            *(uint2*)&g_Ah[m*D4 + 512  + d0 + tx*4] = uh;
            *(uint2*)&g_Ah[m*D4 + 1024 + d0 + tx*4] = uc;
        }
        __syncthreads();
        #pragma unroll
        for (int i = 0; i < 4; i++) rq[i] = rqn[i];
    }
}

// ---------------------------------------------------------------------------
// Kernel 2: h_tilde partials with fused attn softmax  [R10, unchanged]
// ---------------------------------------------------------------------------
__global__ void k_h(const float* __restrict__ contexts) {
    __shared__ float smm[512];
    __shared__ float red[128];
    __shared__ float sa[128];
    __shared__ float part[128];
    int bid = blockIdx.x;
    int cs = bid & 3;
    int dc = (bid >> 2) & 7;
    int b  = bid >> 5;
    int tid = threadIdx.x;
    #pragma unroll
    for (int i = 0; i < 4; i++) smm[tid + i*128] = g_m[b*CC + tid + i*128];
    __syncthreads();
    float mx = fmaxf(fmaxf(smm[tid], smm[tid+128]), fmaxf(smm[tid+256], smm[tid+384]));
    red[tid] = mx; __syncthreads();
    for (int s = 64; s > 0; s >>= 1) {
        if (tid < s) red[tid] = fmaxf(red[tid], red[tid + s]);
        __syncthreads();
    }
    mx = red[0]; __syncthreads();
    float sv = __expf(smm[tid]-mx) + __expf(smm[tid+128]-mx)
             + __expf(smm[tid+256]-mx) + __expf(smm[tid+384]-mx);
    red[tid] = sv; __syncthreads();
    for (int s = 64; s > 0; s >>= 1) {
        if (tid < s) red[tid] += red[tid + s];
        __syncthreads();
    }
    float inv = 1.f / red[0];
    sa[tid] = __expf(smm[cs*128 + tid] - mx) * inv;
    __syncthreads();
    int d = dc*64 + (tid & 63);
    int h = tid >> 6;
    const float* ctx = contexts + ((size_t)b*CC + cs*128 + h*64)*DD;
    float acc = 0.f;
    #pragma unroll 8
    for (int c = 0; c < 64; c++) acc += sa[h*64 + c] * ctx[(size_t)c*DD + d];
    part[tid] = acc;
    __syncthreads();
    if (h == 0) g_hp[((size_t)b*4 + cs)*DD + d] = part[tid] + part[tid + 64];
}

// ---------------------------------------------------------------------------
// Kernel 3: A seg0/seg3 -> fp16, and qac_w -> fp16 (merged)   [R10, unchanged]
// ---------------------------------------------------------------------------
__global__ void k_mm(const float* __restrict__ contexts,
                     const float* __restrict__ qac_w) {
    int bid = blockIdx.x;
    int tid = threadIdx.x;
    if (bid < 8192) {
        int m = bid;
        int b = m >> 9;
        uint2 h4;
        if (tid < 128) {
            int off = tid*4;
            float4 cv = *(const float4*)(contexts + (size_t)m*DD + off);
            h4.x = pack2h(cv.x, cv.y);
            h4.y = pack2h(cv.z, cv.w);
            *(uint2*)&g_Ah[(size_t)m*D4 + off] = h4;
        } else {
            int off = (tid - 128)*4;
            float4 cv = *(const float4*)(contexts + (size_t)m*DD + off);
            const float* hp = g_hp + (size_t)b*4*DD + off;
            float4 h0 = *(const float4*)(hp);
            float4 h1 = *(const float4*)(hp + DD);
            float4 h2 = *(const float4*)(hp + 2*DD);
            float4 h3 = *(const float4*)(hp + 3*DD);
            float hx = h0.x+h1.x+h2.x+h3.x;
            float hy = h0.y+h1.y+h2.y+h3.y;
            float hz = h0.z+h1.z+h2.z+h3.z;
            float hw = h0.w+h1.w+h2.w+h3.w;
            h4.x = pack2h(cv.x*hx, cv.y*hy);
            h4.y = pack2h(cv.z*hz, cv.w*hw);
            *(uint2*)&g_Ah[(size_t)m*D4 + 1536 + off] = h4;
        }
    } else {
        size_t i4 = (size_t)(bid - 8192)*256 + tid;   // D4*D4/4
        float4 v = ((const float4*)qac_w)[i4];
        uint2 h4;
        h4.x = pack2h(v.x, v.y);
        h4.y = pack2h(v.z, v.w);
        ((uint2*)g_Bh)[i4] = h4;
    }
}

// ---------------------------------------------------------------------------
// Kernel 4: mma.sync fp16 GEMM (single term, K = 2048)  [R10 exact, proven]
// CTA 128x128, 8 warps (2Mx4N), warp tile 64x32, 3-stage cp.async, 2 CTA/SM.
// ---------------------------------------------------------------------------
#define ROWB 144
#define ATILE (128*ROWB)         // 18432 B
#define STG1B (2*ATILE)          // 36864 B per stage (A|B)
#define GSMEM2 (3*STG1B)         // 110592 B

__global__ __launch_bounds__(256, 2) void k_gemm_mma(
    const float* __restrict__ bias, float* __restrict__ out) {
    extern __shared__ char smem[];
    uint32_t su = smem_u32(smem);
    int tid  = threadIdx.x;
    int lane = tid & 31;
    int w    = tid >> 5;
    int wm   = w >> 2;          // 0..1
    int wn   = w & 3;           // 0..3
    int n0 = blockIdx.x * 128;
    int m0 = blockIdx.y * 128;

    float acc[4][4][4];
    #pragma unroll
    for (int i = 0; i < 4; i++)
        #pragma unroll
        for (int p = 0; p < 4; p++)
            #pragma unroll
            for (int e = 0; e < 4; e++) acc[i][p][e] = 0.f;

    int lrow = tid >> 3;        // 0..31
    int lchk = tid & 7;         // 16B chunk within 128B row

    auto load_stage = [&](int it, int s) {
        int kbase = it * 64;
        uint32_t sb = su + s*STG1B;
        #pragma unroll
        for (int i = 0; i < 4; i++) {
            int row = lrow + i*32;
            size_t aoff = (size_t)(m0 + row)*D4 + kbase + lchk*8;
            size_t boff = (size_t)(n0 + row)*D4 + kbase + lchk*8;
            uint32_t d = sb + row*ROWB + lchk*16;
            CP16(d,         (const void*)(g_Ah + aoff));
            CP16(d + ATILE, (const void*)(g_Bh + boff));
        }
        asm volatile("cp.async.commit_group;" ::: "memory");
    };

    load_stage(0, 0);
    load_stage(1, 1);

    int lr16 = (lane & 7) + ((lane >> 3) & 1) * 8;   // row 0..15
    int lc16 = lane >> 4;                             // chunk 0/1

    for (int it = 0; it < 32; it++) {
        int s = it % 3;
        if (it < 31) {
            asm volatile("cp.async.wait_group %0;" :: "n"(1) : "memory");
        } else {
            asm volatile("cp.async.wait_group %0;" :: "n"(0) : "memory");
        }
        __syncthreads();

        if (it + 2 < 32) load_stage(it + 2, (it + 2) % 3);

        uint32_t base = su + s*STG1B;
        uint32_t aW = base + (wm*64 + lr16)*ROWB + lc16*16;
        uint32_t bW = base + ATILE + (wn*32 + lr16)*ROWB + lc16*16;

        #pragma unroll
        for (int j = 0; j < 4; j++) {
            uint32_t af[4][4];
            #pragma unroll
            for (int i = 0; i < 4; i++)
                LDSM4(af[i], aW + i*16*ROWB + j*32);
            uint32_t bf[2][4];
            #pragma unroll
            for (int h = 0; h < 2; h++)
                LDSM4(bf[h], bW + h*16*ROWB + j*32);
            #pragma unroll
            for (int i = 0; i < 4; i++)
                #pragma unroll
                for (int p = 0; p < 4; p++)
                    mma16816(acc[i][p], af[i], bf[p>>1][p&1], bf[p>>1][(p&1)+2]);
        }
    }

    // Epilogue
    int g = lane >> 2, t = lane & 3;
    #pragma unroll
    for (int i = 0; i < 4; i++) {
        int row = m0 + wm*64 + i*16 + g;
        #pragma unroll
        for (int p = 0; p < 4; p++) {
            int col = n0 + wn*32 + p*8 + 2*t;
            float b0 = bias[col], b1 = bias[col + 1];
            float2 v0 = make_float2(acc[i][p][0] + b0, acc[i][p][1] + b1);
            float2 v1 = make_float2(acc[i][p][2] + b0, acc[i][p][3] + b1);
            *(float2*)(out + (size_t)row*D4 + col)       = v0;
            *(float2*)(out + (size_t)(row + 8)*D4 + col) = v1;
        }
    }
}

// ---------------------------------------------------------------------------
extern "C" void kernel_launch(void* const* d_in, const int* in_sizes, int n_in,
                              void* d_out, int out_size) {
    const float* questions = (const float*)d_in[0];
    const float* contexts  = (const float*)d_in[1];
    const float* sim_w     = (const float*)d_in[2];
    const float* qac_w     = (const float*)d_in[3];
    const float* qac_b     = (const float*)d_in[4];
    float* out = (float*)d_out;

    cudaFuncSetAttribute(k_gemm_mma, cudaFuncAttributeMaxDynamicSharedMemorySize, GSMEM2);

    k_sim_u<<<256, 256>>>(questions, contexts, sim_w);
    k_h<<<512, 128>>>(contexts);
    k_mm<<<12288, 256>>>(contexts, qac_w);
    k_gemm_mma<<<dim3(16, 64), 256, GSMEM2>>>(qac_b, out);
}